// round 7
// baseline (speedup 1.0000x reference)
#include <cuda_runtime.h>
#include <cuda_bf16.h>
#include <math.h>

// ---------------------------------------------------------------------------
// PhotonicDelayReservoirAdaptive — sparse delay-tap reservoir scan, sm_103a.
//
//   fb[b,s]  = sum_k softmax(tapw)[k] * sum_r h[b, t-d_k, r] * W_fb[k,r,s]
//   h_new    = 0.9*h + 0.1*tanh(x[b,t]*W_in[s] + fb[b,s] + bias[s])
//
// R6 = R3 skeleton (16 clusters x 8 CTAs, 256 thr, 8-lane column groups,
// HW barrier.cluster, L2 pull via __ldcg) + three isolated changes:
//   1. tap-sorted CSR: per column, tap-1 entries first (idx=r), then taps
//      {4,24,96,168} (idx=(k-1)*256+r); segments padded to x16; the taps>=4
//      gather runs 3/4 BEFORE barrier.cluster.wait (rows are >=2 phases old),
//      1/4 after (covers the tap-1 L2 latency).
//   2. one-step register prefetch of the d>=4 rows + x, staged to SMEM at
//      the top of the next iteration (no LDG->STS latency serialization).
//   3. parallel epilogue: lanes 0-3 of each 8-lane group own one batch each
//      (tanh in parallel instead of 4x serial on lane 0).
// ---------------------------------------------------------------------------

#define T_LEN      2048
#define R_DIM      256
#define N_TAPS     5
#define RANKS      8
#define COLS_PER   32
#define BATCH_PER  4
#define CAP        6144
#define NTHREADS   256

// SMEM layout (dynamic):
//   [0,16384)      float4 hist14[1024]   taps {4,24,96,168}, batch-packed
//   [16384,20480)  float4 hist0[256]     tap-1 row, batch-packed
//   [20480,69632)  uint2  csr[CAP]
//   [69632,69764)  int    offA[33]       column segment starts (+total)
//   [69764,69892)  int    offB[32]       tap-1/tap>=4 segment boundary
#define SMEM_H14   0
#define SMEM_H0    16384
#define SMEM_CSR   20480
#define SMEM_OFFA  69632
#define SMEM_OFFB  69764
#define SMEM_BYTES 69892

__device__ __align__(16) uint2 g_entries[RANKS * CAP];
__device__ int g_offA[RANKS * 33];
__device__ int g_offB[RANKS * 32];

// ---------------------------------------------------------------------------
// Builder: 1 CTA, thread = output column s. Two-segment CSR per column
// (tap-1 first, then taps 2..5), softmax tap weight folded into values,
// each segment zero-padded to a multiple of 16 (8 lanes x 2-entry uint4).
// ---------------------------------------------------------------------------
__global__ void build_csr_kernel(const float* __restrict__ W_fb,
                                 const float* __restrict__ tap_weights) {
    __shared__ float tw[N_TAPS];
    __shared__ int p0s[R_DIM], p1s[R_DIM], cstart[R_DIM], cmid[R_DIM];

    const int s = threadIdx.x;

    if (s == 0) {
        float m = tap_weights[0];
        #pragma unroll
        for (int k = 1; k < N_TAPS; k++) m = fmaxf(m, tap_weights[k]);
        float e[N_TAPS]; float sum = 0.f;
        #pragma unroll
        for (int k = 0; k < N_TAPS; k++) { e[k] = expf(tap_weights[k] - m); sum += e[k]; }
        #pragma unroll
        for (int k = 0; k < N_TAPS; k++) tw[k] = e[k] / sum;
    }

    int c0 = 0, c1 = 0;
    for (int r = 0; r < R_DIM; r++)
        c0 += (W_fb[r * R_DIM + s] != 0.f) ? 1 : 0;
    for (int k = 1; k < N_TAPS; k++)
        for (int r = 0; r < R_DIM; r++)
            c1 += (W_fb[(k * R_DIM + r) * R_DIM + s] != 0.f) ? 1 : 0;
    p0s[s] = (c0 + 15) & ~15;
    p1s[s] = (c1 + 15) & ~15;
    __syncthreads();

    if (s < RANKS) {
        int off = 0;
        for (int c = 0; c < COLS_PER; c++) {
            int col = s * COLS_PER + c;
            cstart[col] = off;
            g_offA[s * 33 + c] = off;
            cmid[col] = off + p0s[col];
            g_offB[s * 32 + c] = off + p0s[col];
            off += p0s[col] + p1s[col];
        }
        g_offA[s * 33 + 32] = off;
    }
    __syncthreads();

    const int rank = s >> 5;
    const int base = rank * CAP;
    int p = cstart[s];
    const int mid  = cmid[s];
    const int pend = mid + p1s[s];
    if (pend <= CAP) {
        // tap-1 segment (idx = r into hist0)
        for (int r = 0; r < R_DIM; r++) {
            float v = W_fb[r * R_DIM + s];
            if (v != 0.f)
                g_entries[base + p++] = make_uint2(__float_as_uint(v * tw[0]), (unsigned)r);
        }
        for (; p < mid; p++) g_entries[base + p] = make_uint2(0u, 0u);
        // taps 2..5 (idx = (k-1)*256 + r into hist14)
        for (int k = 1; k < N_TAPS; k++) {
            const float twk = tw[k];
            for (int r = 0; r < R_DIM; r++) {
                float v = W_fb[(k * R_DIM + r) * R_DIM + s];
                if (v != 0.f)
                    g_entries[base + p++] =
                        make_uint2(__float_as_uint(v * twk), (unsigned)((k - 1) * R_DIM + r));
            }
        }
        for (; p < pend; p++) g_entries[base + p] = make_uint2(0u, 0u);
    }
}

// ---------------------------------------------------------------------------
// Main sequential-scan kernel.
// ---------------------------------------------------------------------------
__global__ void __cluster_dims__(RANKS, 1, 1) __launch_bounds__(NTHREADS, 1)
reservoir_kernel(const float* __restrict__ x,
                 const float* __restrict__ W_in,
                 const float* __restrict__ bias,
                 float* __restrict__ out) {
    extern __shared__ char smem_raw[];
    float4* hist14 = (float4*)(smem_raw + SMEM_H14);   // [1024]
    float4* hist0  = (float4*)(smem_raw + SMEM_H0);    // [256]
    uint2*  csr    = (uint2*) (smem_raw + SMEM_CSR);   // [CAP]
    int*    offA   = (int*)   (smem_raw + SMEM_OFFA);  // [33]
    int*    offB   = (int*)   (smem_raw + SMEM_OFFB);  // [32]

    const int tid  = threadIdx.x;
    const unsigned rank = blockIdx.x & (RANKS - 1);
    const int b0 = (int)(blockIdx.x >> 3) * BATCH_PER;

    // ---- prologue ----
    if (tid < 33) offA[tid] = g_offA[rank * 33 + tid];
    if (tid < 32) offB[tid] = g_offB[rank * 32 + tid];
    {
        const uint4* src = (const uint4*)(g_entries + rank * CAP);
        uint4* dst = (uint4*)csr;
        for (int i = tid; i < CAP / 2; i += NTHREADS) dst[i] = src[i];
    }

    const int colg  = tid >> 3;               // column within slice
    const int lane8 = tid & 7;                // 8-way nnz split
    const int s     = (int)rank * COLS_PER + colg;
    const float w_in_s = W_in[s];
    const float bias_s = bias[s];
    const size_t bstride = (size_t)T_LEN * R_DIM;
    const float* outr0 = out + (size_t)b0 * bstride + tid;   // row r = tid

    float h = 0.f;   // lane8<4: state of batch lane8 for column s
    float en[4][BATCH_PER];                  // prefetched d>=4 rows for step t
    #pragma unroll
    for (int k = 0; k < 4; k++)
        #pragma unroll
        for (int bb = 0; bb < BATCH_PER; bb++) en[k][bb] = 0.f;
    float xcur = (lane8 < BATCH_PER) ? __ldg(x + (size_t)(b0 + lane8) * T_LEN) : 0.f;

    __syncthreads();
    const int segA = offA[colg];              // tap-1 segment start
    const int segB = offB[colg];              // taps>=4 segment start
    const int segE = offA[colg + 1];          // end
    const int segM = segB + ((((segE - segB) * 3) / 4) & ~15);  // 3/4 split

    asm volatile("barrier.cluster.arrive.aligned;" ::: "memory");

    for (int t = 0; t < T_LEN; t++) {
        // 1. stage hist14 for THIS step from prev-iteration prefetch regs
        #pragma unroll
        for (int k = 0; k < 4; k++)
            hist14[k * R_DIM + tid] =
                make_float4(en[k][0], en[k][1], en[k][2], en[k][3]);

        // 2. issue prefetch for step t+1 (rows <= t-3: visible since the
        //    wait of step t-1; latency hides under the big gather below)
        float xn = 0.f;
        {
            const int tn = t + 1;
            const int rows[4] = { tn - 4, tn - 24, tn - 96, tn - 168 };
            #pragma unroll
            for (int k = 0; k < 4; k++) {
                const int rk = rows[k];
                if (rk >= 0 && tn < T_LEN) {
                    const float* base = outr0 + (size_t)rk * R_DIM;
                    #pragma unroll
                    for (int bb = 0; bb < BATCH_PER; bb++)
                        en[k][bb] = __ldcg(base + (size_t)bb * bstride);
                } else {
                    #pragma unroll
                    for (int bb = 0; bb < BATCH_PER; bb++) en[k][bb] = 0.f;
                }
            }
            if (lane8 < BATCH_PER && tn < T_LEN)
                xn = __ldg(x + (size_t)(b0 + lane8) * T_LEN + tn);
        }

        __syncthreads();   // hist14 staged CTA-wide

        // 3. big gather, first 3/4 of taps>=4 (pre-wait; 2-entry uint4, dual acc)
        float4 a0 = make_float4(0.f, 0.f, 0.f, 0.f);
        float4 a1 = make_float4(0.f, 0.f, 0.f, 0.f);
        for (int j = segB + lane8 * 2; j < segM; j += 16) {
            const uint4 e = *(const uint4*)(csr + j);
            const float4 u = hist14[e.y];
            const float4 v = hist14[e.w];
            const float f0 = __uint_as_float(e.x);
            const float f1 = __uint_as_float(e.z);
            a0.x = fmaf(f0, u.x, a0.x); a0.y = fmaf(f0, u.y, a0.y);
            a0.z = fmaf(f0, u.z, a0.z); a0.w = fmaf(f0, u.w, a0.w);
            a1.x = fmaf(f1, v.x, a1.x); a1.y = fmaf(f1, v.y, a1.y);
            a1.z = fmaf(f1, v.z, a1.z); a1.w = fmaf(f1, v.w, a1.w);
        }

        // 4. wait: row t-1 becomes visible (peers had ~1 gather of slack)
        asm volatile("barrier.cluster.wait.aligned;" ::: "memory");

        // 5. issue tap-1 loads; cover latency with the remaining 1/4 gather
        float t1[BATCH_PER];
        if (t > 0) {
            const float* base = outr0 + (size_t)(t - 1) * R_DIM;
            #pragma unroll
            for (int bb = 0; bb < BATCH_PER; bb++)
                t1[bb] = __ldcg(base + (size_t)bb * bstride);
        } else {
            #pragma unroll
            for (int bb = 0; bb < BATCH_PER; bb++) t1[bb] = 0.f;
        }

        for (int j = segM + lane8 * 2; j < segE; j += 16) {
            const uint4 e = *(const uint4*)(csr + j);
            const float4 u = hist14[e.y];
            const float4 v = hist14[e.w];
            const float f0 = __uint_as_float(e.x);
            const float f1 = __uint_as_float(e.z);
            a0.x = fmaf(f0, u.x, a0.x); a0.y = fmaf(f0, u.y, a0.y);
            a0.z = fmaf(f0, u.z, a0.z); a0.w = fmaf(f0, u.w, a0.w);
            a1.x = fmaf(f1, v.x, a1.x); a1.y = fmaf(f1, v.y, a1.y);
            a1.z = fmaf(f1, v.z, a1.z); a1.w = fmaf(f1, v.w, a1.w);
        }

        // 6. stage tap-1 row, then gather it
        hist0[tid] = make_float4(t1[0], t1[1], t1[2], t1[3]);
        __syncthreads();

        for (int j = segA + lane8 * 2; j < segB; j += 16) {
            const uint4 e = *(const uint4*)(csr + j);
            const float4 u = hist0[e.y];
            const float4 v = hist0[e.w];
            const float f0 = __uint_as_float(e.x);
            const float f1 = __uint_as_float(e.z);
            a0.x = fmaf(f0, u.x, a0.x); a0.y = fmaf(f0, u.y, a0.y);
            a0.z = fmaf(f0, u.z, a0.z); a0.w = fmaf(f0, u.w, a0.w);
            a1.x = fmaf(f1, v.x, a1.x); a1.y = fmaf(f1, v.y, a1.y);
            a1.z = fmaf(f1, v.z, a1.z); a1.w = fmaf(f1, v.w, a1.w);
        }

        float4 acc;
        acc.x = a0.x + a1.x; acc.y = a0.y + a1.y;
        acc.z = a0.z + a1.z; acc.w = a0.w + a1.w;

        // 7. reduce across the 8-lane group
        #pragma unroll
        for (int m = 1; m < 8; m <<= 1) {
            acc.x += __shfl_xor_sync(0xffffffffu, acc.x, m);
            acc.y += __shfl_xor_sync(0xffffffffu, acc.y, m);
            acc.z += __shfl_xor_sync(0xffffffffu, acc.z, m);
            acc.w += __shfl_xor_sync(0xffffffffu, acc.w, m);
        }

        // 8. parallel epilogue: lane bb<4 owns batch bb
        if (lane8 < BATCH_PER) {
            const float myacc = (lane8 == 0) ? acc.x :
                                (lane8 == 1) ? acc.y :
                                (lane8 == 2) ? acc.z : acc.w;
            h = 0.9f * h + 0.1f * tanhf(fmaf(xcur, w_in_s, myacc) + bias_s);
            out[(size_t)(b0 + lane8) * bstride + (size_t)t * R_DIM + s] = h;
        }
        xcur = xn;

        // 9. release row t to the cluster
        asm volatile("barrier.cluster.arrive.aligned;" ::: "memory");
    }
    asm volatile("barrier.cluster.wait.aligned;" ::: "memory");
}

// ---------------------------------------------------------------------------
extern "C" void kernel_launch(void* const* d_in, const int* in_sizes, int n_in,
                              void* d_out, int out_size) {
    const float* x           = (const float*)d_in[0];  // (64, 2048, 1)
    const float* W_in        = (const float*)d_in[1];  // (256, 1)
    const float* W_fb        = (const float*)d_in[2];  // (5, 256, 256)
    const float* tap_weights = (const float*)d_in[3];  // (5,)
    const float* bias        = (const float*)d_in[4];  // (256,)
    float* out = (float*)d_out;                        // (64, 2048, 256)

    (void)in_sizes; (void)n_in; (void)out_size;

    cudaFuncSetAttribute(reservoir_kernel,
                         cudaFuncAttributeMaxDynamicSharedMemorySize, SMEM_BYTES);

    build_csr_kernel<<<1, NTHREADS>>>(W_fb, tap_weights);
    reservoir_kernel<<<16 * RANKS, NTHREADS, SMEM_BYTES>>>(x, W_in, bias, out);
}